// round 1
// baseline (speedup 1.0000x reference)
#include <cuda_runtime.h>
#include <cuda_fp16.h>
#include <mma.h>
#include <math.h>
#include <stdint.h>

using namespace nvcuda;

// ---------------- problem constants ----------------
#define D_DIM   2048
#define I_DIM   5632
#define NE      8
#define T_TOK   8192
#define SHARED_BASE 17408          // max padded expert slots: 16384 + 8*127 -> round to 17408
#define TOT_ROWS   (SHARED_BASE + T_TOK)   // 25600

// ---------------- static device scratch (no allocs allowed) ----------------
__device__ __half g_Xh[(size_t)T_TOK * D_DIM];
__device__ __half g_Wg[(size_t)NE * I_DIM * D_DIM];
__device__ __half g_Wu[(size_t)NE * I_DIM * D_DIM];
__device__ __half g_Wd[(size_t)NE * D_DIM * I_DIM];
__device__ __half g_Sg[(size_t)I_DIM * D_DIM];
__device__ __half g_Su[(size_t)I_DIM * D_DIM];
__device__ __half g_Sd[(size_t)D_DIM * I_DIM];
__device__ __half g_H [(size_t)TOT_ROWS * I_DIM];   // intermediate silu(g)*u, fp16
__device__ float  g_Y [(size_t)TOT_ROWS * D_DIM];   // down-proj outputs, f32

__device__ int    g_cnt[NE];
__device__ int    g_off[NE + 1];
__device__ int    g_cur[NE];
__device__ float  g_psum[NE];
__device__ int    g_topi[T_TOK * 2];
__device__ float  g_topw[T_TOK * 2];
__device__ int    g_slot[T_TOK * 2];
__device__ int    g_rowlist[SHARED_BASE];

// ---------------- helpers ----------------
__device__ __forceinline__ void cpa16(__half* dst, const __half* src, int srcsize) {
    uint32_t d = (uint32_t)__cvta_generic_to_shared(dst);
    asm volatile("cp.async.cg.shared.global [%0], [%1], 16, %2;\n"
                 :: "r"(d), "l"(src), "r"(srcsize));
}
template <int N>
__device__ __forceinline__ void cp_wait() {
    asm volatile("cp.async.wait_group %0;\n" :: "n"(N));
}
__device__ __forceinline__ void cp_commit() {
    asm volatile("cp.async.commit_group;\n");
}

// ---------------- init ----------------
__global__ void init_kernel() {
    int i = threadIdx.x;
    if (i < NE) { g_cnt[i] = 0; g_psum[i] = 0.0f; }
}

// ---------------- f32 -> fp16 conversion ----------------
__device__ __forceinline__ __half* cvt_dst(int w) {
    switch (w) {
        case 0: return g_Xh;
        case 1: return g_Wg;
        case 2: return g_Wu;
        case 3: return g_Wd;
        case 4: return g_Sg;
        case 5: return g_Su;
        default: return g_Sd;
    }
}
__global__ void cvt_kernel(const float* __restrict__ src, int which, int n) {
    __half* dst = cvt_dst(which);
    int stride = gridDim.x * blockDim.x;
    for (int i = blockIdx.x * blockDim.x + threadIdx.x; i * 4 < n; i += stride) {
        int j = i * 4;
        float4 v = *(const float4*)(src + j);
        __half2* d2 = (__half2*)(dst + j);
        d2[0] = __floats2half2_rn(v.x, v.y);
        d2[1] = __floats2half2_rn(v.z, v.w);
    }
}

// ---------------- router ----------------
__global__ void router_kernel(const float* __restrict__ x, const float* __restrict__ gw) {
    __shared__ int   scnt[NE];
    __shared__ float sps[NE];
    int tid = threadIdx.x;
    if (tid < NE) { scnt[tid] = 0; sps[tid] = 0.0f; }
    __syncthreads();

    int warp = tid >> 5, lane = tid & 31;
    int t = blockIdx.x * 8 + warp;

    float acc[NE];
#pragma unroll
    for (int e = 0; e < NE; e++) acc[e] = 0.0f;

    const float* xp = x + (size_t)t * D_DIM;
    for (int k = lane; k < D_DIM; k += 32) {
        float xv = xp[k];
#pragma unroll
        for (int e = 0; e < NE; e++) acc[e] += xv * __ldg(&gw[e * D_DIM + k]);
    }
#pragma unroll
    for (int e = 0; e < NE; e++) {
#pragma unroll
        for (int o = 16; o; o >>= 1) acc[e] += __shfl_down_sync(0xffffffffu, acc[e], o);
    }

    if (lane == 0) {
        // top-2 (stable: first index wins ties, matching jax top_k)
        int i0 = 0; float v0 = acc[0];
#pragma unroll
        for (int e = 1; e < NE; e++) if (acc[e] > v0) { v0 = acc[e]; i0 = e; }
        int i1 = -1; float v1 = -1e30f;
#pragma unroll
        for (int e = 0; e < NE; e++) if (e != i0 && acc[e] > v1) { v1 = acc[e]; i1 = e; }

        float e1 = expf(v1 - v0);
        float w0 = 1.0f / (1.0f + e1);
        float w1 = e1 * w0;
        g_topi[2 * t]     = i0;  g_topi[2 * t + 1] = i1;
        g_topw[2 * t]     = w0;  g_topw[2 * t + 1] = w1;
        atomicAdd(&scnt[i0], 1);
        atomicAdd(&scnt[i1], 1);

        // full softmax for mean_prob
        float m = acc[0];
#pragma unroll
        for (int e = 1; e < NE; e++) m = fmaxf(m, acc[e]);
        float s = 0.0f;
        float pe[NE];
#pragma unroll
        for (int e = 0; e < NE; e++) { pe[e] = expf(acc[e] - m); s += pe[e]; }
        float inv = 1.0f / s;
#pragma unroll
        for (int e = 0; e < NE; e++) atomicAdd(&sps[e], pe[e] * inv);
    }
    __syncthreads();
    if (tid < NE) {
        atomicAdd(&g_cnt[tid], scnt[tid]);
        atomicAdd(&g_psum[tid], sps[tid]);
    }
}

// ---------------- offsets scan + aux loss ----------------
__global__ void scan_kernel(float* __restrict__ out, int out_size) {
    if (threadIdx.x == 0 && blockIdx.x == 0) {
        int o = 0;
        for (int e = 0; e < NE; e++) {
            g_off[e] = o;
            g_cur[e] = o;
            o += (g_cnt[e] + 127) & ~127;
        }
        g_off[NE] = o;
        float s = 0.0f;
        for (int e = 0; e < NE; e++) s += (float)g_cnt[e] * g_psum[e];
        float aux = 0.01f * (float)NE * s / ((float)T_TOK * (float)T_TOK);
        if (out_size > T_TOK * D_DIM) out[out_size - 1] = aux;
    }
}

// ---------------- token -> slot fill ----------------
__global__ void fill_kernel() {
    int t = blockIdx.x * blockDim.x + threadIdx.x;
    if (t >= T_TOK) return;
#pragma unroll
    for (int k = 0; k < 2; k++) {
        int e = g_topi[2 * t + k];
        int pos = atomicAdd(&g_cur[e], 1);
        g_rowlist[pos] = t;
        g_slot[2 * t + k] = pos;
    }
}

// ---------------- GEMM1: H = silu(X@Wg^T) * (X@Wu^T)  (fp16 out) ----------------
// CTA tile: M=128, N=64 (per matrix, gate+up both), K-step 32. 8 warps 4x2, warp 32x32.
__global__ void __launch_bounds__(256) gemm1_kernel() {
    const int p  = blockIdx.y >> 6;
    const int rt = blockIdx.y & 63;
    int base, cnt;
    if (p < NE) { base = g_off[p]; cnt = g_cnt[p]; }
    else        { base = SHARED_BASE; cnt = T_TOK; }
    if (rt * 128 >= cnt) return;

    const int col0 = blockIdx.x * 64;
    const __half *Bg, *Bu;
    if (p < NE) {
        size_t wo = (size_t)p * I_DIM * D_DIM;
        Bg = g_Wg + wo; Bu = g_Wu + wo;
    } else { Bg = g_Sg; Bu = g_Su; }

    __shared__ __align__(16) __half smem_h[20480];   // 2 stages x (A 128x40 + Bg 64x40 + Bu 64x40)

    const int tid = threadIdx.x;
    const int seg = tid & 3;
    const int ar  = tid >> 2;             // 0..63

    int gr0 = rt * 128 + ar;
    int gr1 = gr0 + 64;
    int vs0 = 16, vs1 = 16;
    int tok0, tok1;
    if (p < NE) {
        vs0 = (gr0 < cnt) ? 16 : 0;
        vs1 = (gr1 < cnt) ? 16 : 0;
        tok0 = vs0 ? g_rowlist[base + gr0] : 0;
        tok1 = vs1 ? g_rowlist[base + gr1] : 0;
    } else { tok0 = gr0; tok1 = gr1; }

    const __half* a0 = g_Xh + (size_t)tok0 * D_DIM + seg * 8;
    const __half* a1 = g_Xh + (size_t)tok1 * D_DIM + seg * 8;
    const __half* b0 = Bg + (size_t)(col0 + ar) * D_DIM + seg * 8;
    const __half* b1 = Bu + (size_t)(col0 + ar) * D_DIM + seg * 8;

    const int dA0 = ar * 40 + seg * 8;
    const int dA1 = dA0 + 64 * 40;
    const int dBg = 5120 + ar * 40 + seg * 8;
    const int dBu = 7680 + ar * 40 + seg * 8;

    const int wid = tid >> 5, lane = tid & 31;
    const int wm = wid >> 1, wn = wid & 1;

    wmma::fragment<wmma::accumulator, 16, 16, 16, float> accG[2][2], accU[2][2];
#pragma unroll
    for (int i = 0; i < 2; i++)
#pragma unroll
        for (int j = 0; j < 2; j++) {
            wmma::fill_fragment(accG[i][j], 0.0f);
            wmma::fill_fragment(accU[i][j], 0.0f);
        }

    // prologue
    {
        __half* bp = smem_h;
        cpa16(bp + dA0, a0, vs0); cpa16(bp + dA1, a1, vs1);
        cpa16(bp + dBg, b0, 16);  cpa16(bp + dBu, b1, 16);
        a0 += 32; a1 += 32; b0 += 32; b1 += 32;
        cp_commit();
    }

    const int nK = D_DIM / 32;   // 64
    for (int kt = 0; kt < nK; ++kt) {
        if (kt + 1 < nK) {
            __half* bp = smem_h + ((kt + 1) & 1) * 10240;
            cpa16(bp + dA0, a0, vs0); cpa16(bp + dA1, a1, vs1);
            cpa16(bp + dBg, b0, 16);  cpa16(bp + dBu, b1, 16);
            a0 += 32; a1 += 32; b0 += 32; b1 += 32;
            cp_commit();
            cp_wait<1>();
        } else {
            cp_wait<0>();
        }
        __syncthreads();
        const __half* A  = smem_h + (kt & 1) * 10240;
        const __half* BG = A + 5120;
        const __half* BU = A + 7680;
#pragma unroll
        for (int kk = 0; kk < 32; kk += 16) {
            wmma::fragment<wmma::matrix_a, 16, 16, 16, __half, wmma::row_major> af[2];
            wmma::fragment<wmma::matrix_b, 16, 16, 16, __half, wmma::col_major> bgf[2], buf_[2];
            wmma::load_matrix_sync(af[0], A + (wm * 32 + 0) * 40 + kk, 40);
            wmma::load_matrix_sync(af[1], A + (wm * 32 + 16) * 40 + kk, 40);
            wmma::load_matrix_sync(bgf[0], BG + (wn * 32 + 0) * 40 + kk, 40);
            wmma::load_matrix_sync(bgf[1], BG + (wn * 32 + 16) * 40 + kk, 40);
            wmma::load_matrix_sync(buf_[0], BU + (wn * 32 + 0) * 40 + kk, 40);
            wmma::load_matrix_sync(buf_[1], BU + (wn * 32 + 16) * 40 + kk, 40);
#pragma unroll
            for (int i = 0; i < 2; i++)
#pragma unroll
                for (int j = 0; j < 2; j++) {
                    wmma::mma_sync(accG[i][j], af[i], bgf[j], accG[i][j]);
                    wmma::mma_sync(accU[i][j], af[i], buf_[j], accU[i][j]);
                }
        }
        __syncthreads();
    }

    // epilogue: h = silu(g) * u, convert to fp16, write H
    float* scr = reinterpret_cast<float*>(smem_h) + wid * (32 * 36);
    wmma::fragment<wmma::accumulator, 16, 16, 16, float> hf;
#pragma unroll
    for (int i = 0; i < 2; i++)
#pragma unroll
        for (int j = 0; j < 2; j++) {
#pragma unroll
            for (int e = 0; e < hf.num_elements; e++) {
                float g = accG[i][j].x[e];
                float u = accU[i][j].x[e];
                hf.x[e] = (g / (1.0f + __expf(-g))) * u;
            }
            wmma::store_matrix_sync(scr + (i * 16) * 36 + j * 16, hf, 36, wmma::mem_row_major);
        }
    __syncwarp();

    size_t hrow = (size_t)base + rt * 128 + wm * 32 + lane;
    const float* srow = scr + lane * 36;
    __half2 hh[16];
#pragma unroll
    for (int c = 0; c < 16; c++) hh[c] = __floats2half2_rn(srow[2 * c], srow[2 * c + 1]);
    uint4* dst = (uint4*)(g_H + hrow * I_DIM + col0 + wn * 32);
    const uint4* s4 = (const uint4*)hh;
    dst[0] = s4[0]; dst[1] = s4[1]; dst[2] = s4[2]; dst[3] = s4[3];
}

// ---------------- GEMM2: Y = H @ Wd^T (f32 out) ----------------
// CTA tile: M=128, N=128, K-step 32. 8 warps 4x2, warp 32x64.
__global__ void __launch_bounds__(256) gemm2_kernel() {
    const int p  = blockIdx.y >> 6;
    const int rt = blockIdx.y & 63;
    int base, cnt;
    if (p < NE) { base = g_off[p]; cnt = g_cnt[p]; }
    else        { base = SHARED_BASE; cnt = T_TOK; }
    if (rt * 128 >= cnt) return;

    const int col0 = blockIdx.x * 128;
    const __half* Bd = (p < NE) ? (g_Wd + (size_t)p * D_DIM * I_DIM) : g_Sd;

    __shared__ __align__(16) __half smem_h[20480];   // 2 stages x (A 128x40 + B 128x40)

    const int tid = threadIdx.x;
    const int seg = tid & 3;
    const int ar  = tid >> 2;

    const __half* a0 = g_H + (size_t)(base + rt * 128 + ar) * I_DIM + seg * 8;
    const __half* a1 = a0 + (size_t)64 * I_DIM;
    const __half* b0 = Bd + (size_t)(col0 + ar) * I_DIM + seg * 8;
    const __half* b1 = b0 + (size_t)64 * I_DIM;

    const int dA0 = ar * 40 + seg * 8;
    const int dA1 = dA0 + 64 * 40;
    const int dB0 = 5120 + ar * 40 + seg * 8;
    const int dB1 = dB0 + 64 * 40;

    const int wid = tid >> 5;
    const int wm = wid >> 1, wn = wid & 1;

    wmma::fragment<wmma::accumulator, 16, 16, 16, float> acc[2][4];
#pragma unroll
    for (int i = 0; i < 2; i++)
#pragma unroll
        for (int j = 0; j < 4; j++) wmma::fill_fragment(acc[i][j], 0.0f);

    {
        __half* bp = smem_h;
        cpa16(bp + dA0, a0, 16); cpa16(bp + dA1, a1, 16);
        cpa16(bp + dB0, b0, 16); cpa16(bp + dB1, b1, 16);
        a0 += 32; a1 += 32; b0 += 32; b1 += 32;
        cp_commit();
    }

    const int nK = I_DIM / 32;   // 176
    for (int kt = 0; kt < nK; ++kt) {
        if (kt + 1 < nK) {
            __half* bp = smem_h + ((kt + 1) & 1) * 10240;
            cpa16(bp + dA0, a0, 16); cpa16(bp + dA1, a1, 16);
            cpa16(bp + dB0, b0, 16); cpa16(bp + dB1, b1, 16);
            a0 += 32; a1 += 32; b0 += 32; b1 += 32;
            cp_commit();
            cp_wait<1>();
        } else {
            cp_wait<0>();
        }
        __syncthreads();
        const __half* A = smem_h + (kt & 1) * 10240;
        const __half* B = A + 5120;
#pragma unroll
        for (int kk = 0; kk < 32; kk += 16) {
            wmma::fragment<wmma::matrix_a, 16, 16, 16, __half, wmma::row_major> af[2];
            wmma::fragment<wmma::matrix_b, 16, 16, 16, __half, wmma::col_major> bf[4];
            wmma::load_matrix_sync(af[0], A + (wm * 32 + 0) * 40 + kk, 40);
            wmma::load_matrix_sync(af[1], A + (wm * 32 + 16) * 40 + kk, 40);
#pragma unroll
            for (int j = 0; j < 4; j++)
                wmma::load_matrix_sync(bf[j], B + (wn * 64 + j * 16) * 40 + kk, 40);
#pragma unroll
            for (int i = 0; i < 2; i++)
#pragma unroll
                for (int j = 0; j < 4; j++)
                    wmma::mma_sync(acc[i][j], af[i], bf[j], acc[i][j]);
        }
        __syncthreads();
    }

    const int rowb = base + rt * 128 + wm * 32;
    const int colb = col0 + wn * 64;
#pragma unroll
    for (int i = 0; i < 2; i++)
#pragma unroll
        for (int j = 0; j < 4; j++)
            wmma::store_matrix_sync(&g_Y[(size_t)(rowb + i * 16) * D_DIM + colb + j * 16],
                                    acc[i][j], D_DIM, wmma::mem_row_major);
}

// ---------------- combine ----------------
__global__ void combine_kernel(float* __restrict__ out) {
    const float4* Y4 = (const float4*)g_Y;
    float4* o4 = (float4*)out;
    int stride = gridDim.x * blockDim.x;
    const int total = T_TOK * (D_DIM / 4);
    for (int i = blockIdx.x * blockDim.x + threadIdx.x; i < total; i += stride) {
        int t = i >> 9;       // D/4 = 512
        int d = i & 511;
        int s0 = g_slot[2 * t], s1 = g_slot[2 * t + 1];
        float w0 = g_topw[2 * t], w1 = g_topw[2 * t + 1];
        float4 ys = Y4[(size_t)(SHARED_BASE + t) * 512 + d];
        float4 y0 = Y4[(size_t)s0 * 512 + d];
        float4 y1 = Y4[(size_t)s1 * 512 + d];
        float4 r;
        r.x = ys.x + w0 * y0.x + w1 * y1.x;
        r.y = ys.y + w0 * y0.y + w1 * y1.y;
        r.z = ys.z + w0 * y0.z + w1 * y1.z;
        r.w = ys.w + w0 * y0.w + w1 * y1.w;
        o4[i] = r;
    }
}

// ---------------- launch ----------------
extern "C" void kernel_launch(void* const* d_in, const int* in_sizes, int n_in,
                              void* d_out, int out_size) {
    const float* x  = (const float*)d_in[0];
    const float* gw = (const float*)d_in[1];
    const float* eg = (const float*)d_in[2];
    const float* eu = (const float*)d_in[3];
    const float* ed = (const float*)d_in[4];
    const float* sg = (const float*)d_in[5];
    const float* su = (const float*)d_in[6];
    const float* sd = (const float*)d_in[7];
    float* out = (float*)d_out;

    init_kernel<<<1, 32>>>();

    cvt_kernel<<<4096, 256>>>(x,  0, T_TOK * D_DIM);
    cvt_kernel<<<8192, 256>>>(eg, 1, NE * I_DIM * D_DIM);
    cvt_kernel<<<8192, 256>>>(eu, 2, NE * I_DIM * D_DIM);
    cvt_kernel<<<8192, 256>>>(ed, 3, NE * D_DIM * I_DIM);
    cvt_kernel<<<2048, 256>>>(sg, 4, I_DIM * D_DIM);
    cvt_kernel<<<2048, 256>>>(su, 5, I_DIM * D_DIM);
    cvt_kernel<<<2048, 256>>>(sd, 6, D_DIM * I_DIM);

    router_kernel<<<1024, 256>>>(x, gw);
    scan_kernel<<<1, 32>>>(out, out_size);
    fill_kernel<<<32, 256>>>();

    gemm1_kernel<<<dim3(I_DIM / 64, 9 * 64), 256>>>();
    gemm2_kernel<<<dim3(D_DIM / 128, 9 * 64), 256>>>();

    combine_kernel<<<8192, 256>>>(out);
}

// round 4
// speedup vs baseline: 1.2552x; 1.2552x over previous
#include <cuda_runtime.h>
#include <cuda_fp16.h>
#include <mma.h>
#include <math.h>
#include <stdint.h>

using namespace nvcuda;

// ---------------- problem constants ----------------
#define D_DIM   2048
#define I_DIM   5632
#define NE      8
#define T_TOK   8192
#define EXP_TILES  136
#define SHARED_BASE (EXP_TILES * 128)          // 17408
#define TILES_TOTAL (EXP_TILES + T_TOK / 128)  // 200
#define TOT_ROWS   (SHARED_BASE + T_TOK)       // 25600

#define ST 4                     // pipeline stages
#define STAGE_HALFS 10240        // per-stage smem halfs (20 KB)
#define SMEM_DYN    (ST * STAGE_HALFS * 2)     // 81920 B

// ---------------- static device scratch ----------------
__device__ __half g_Xh[(size_t)T_TOK * D_DIM];
__device__ __half g_Xg[(size_t)SHARED_BASE * D_DIM];   // gathered + zero-padded expert A
__device__ __half g_Wg[(size_t)NE * I_DIM * D_DIM];
__device__ __half g_Wu[(size_t)NE * I_DIM * D_DIM];
__device__ __half g_Wd[(size_t)NE * D_DIM * I_DIM];
__device__ __half g_Sg[(size_t)I_DIM * D_DIM];
__device__ __half g_Su[(size_t)I_DIM * D_DIM];
__device__ __half g_Sd[(size_t)D_DIM * I_DIM];
__device__ __half g_H [(size_t)TOT_ROWS * I_DIM];
__device__ float  g_Y [(size_t)TOT_ROWS * D_DIM];

__device__ int    g_cnt[NE];
__device__ int    g_off[NE + 1];
__device__ int    g_cur[NE];
__device__ float  g_psum[NE];
__device__ int    g_topi[T_TOK * 2];
__device__ float  g_topw[T_TOK * 2];
__device__ int    g_slot[T_TOK * 2];
__device__ int    g_rowlist[SHARED_BASE];

// ---------------- helpers ----------------
__device__ __forceinline__ void cpa16(uint32_t dst, const __half* src) {
    asm volatile("cp.async.cg.shared.global [%0], [%1], 16;\n" :: "r"(dst), "l"(src));
}
template <int N>
__device__ __forceinline__ void cp_wait() {
    asm volatile("cp.async.wait_group %0;\n" :: "n"(N));
}
__device__ __forceinline__ void cp_commit() {
    asm volatile("cp.async.commit_group;\n");
}

// ---------------- init ----------------
__global__ void init_kernel() {
    int i = threadIdx.x;
    if (i < NE) { g_cnt[i] = 0; g_psum[i] = 0.0f; }
}

// ---------------- f32 -> fp16 conversion ----------------
__device__ __forceinline__ __half* cvt_dst(int w) {
    switch (w) {
        case 0: return g_Xh;
        case 1: return g_Wg;
        case 2: return g_Wu;
        case 3: return g_Wd;
        case 4: return g_Sg;
        case 5: return g_Su;
        default: return g_Sd;
    }
}
__global__ void cvt_kernel(const float* __restrict__ src, int which, int n) {
    __half* dst = cvt_dst(which);
    int stride = gridDim.x * blockDim.x;
    for (int i = blockIdx.x * blockDim.x + threadIdx.x; i * 4 < n; i += stride) {
        int j = i * 4;
        float4 v = *(const float4*)(src + j);
        __half2* d2 = (__half2*)(dst + j);
        d2[0] = __floats2half2_rn(v.x, v.y);
        d2[1] = __floats2half2_rn(v.z, v.w);
    }
}

// ---------------- router ----------------
__global__ void router_kernel(const float* __restrict__ x, const float* __restrict__ gw) {
    __shared__ int   scnt[NE];
    __shared__ float sps[NE];
    int tid = threadIdx.x;
    if (tid < NE) { scnt[tid] = 0; sps[tid] = 0.0f; }
    __syncthreads();

    int warp = tid >> 5, lane = tid & 31;
    int t = blockIdx.x * 8 + warp;

    float acc[NE];
#pragma unroll
    for (int e = 0; e < NE; e++) acc[e] = 0.0f;

    const float* xp = x + (size_t)t * D_DIM;
    for (int k = lane; k < D_DIM; k += 32) {
        float xv = xp[k];
#pragma unroll
        for (int e = 0; e < NE; e++) acc[e] += xv * __ldg(&gw[e * D_DIM + k]);
    }
#pragma unroll
    for (int e = 0; e < NE; e++) {
#pragma unroll
        for (int o = 16; o; o >>= 1) acc[e] += __shfl_down_sync(0xffffffffu, acc[e], o);
    }

    if (lane == 0) {
        int i0 = 0; float v0 = acc[0];
#pragma unroll
        for (int e = 1; e < NE; e++) if (acc[e] > v0) { v0 = acc[e]; i0 = e; }
        int i1 = -1; float v1 = -1e30f;
#pragma unroll
        for (int e = 0; e < NE; e++) if (e != i0 && acc[e] > v1) { v1 = acc[e]; i1 = e; }

        float e1 = expf(v1 - v0);
        float w0 = 1.0f / (1.0f + e1);
        float w1 = e1 * w0;
        g_topi[2 * t]     = i0;  g_topi[2 * t + 1] = i1;
        g_topw[2 * t]     = w0;  g_topw[2 * t + 1] = w1;
        atomicAdd(&scnt[i0], 1);
        atomicAdd(&scnt[i1], 1);

        float m = acc[0];
#pragma unroll
        for (int e = 1; e < NE; e++) m = fmaxf(m, acc[e]);
        float s = 0.0f;
        float pe[NE];
#pragma unroll
        for (int e = 0; e < NE; e++) { pe[e] = expf(acc[e] - m); s += pe[e]; }
        float inv = 1.0f / s;
#pragma unroll
        for (int e = 0; e < NE; e++) atomicAdd(&sps[e], pe[e] * inv);
    }
    __syncthreads();
    if (tid < NE) {
        atomicAdd(&g_cnt[tid], scnt[tid]);
        atomicAdd(&g_psum[tid], sps[tid]);
    }
}

// ---------------- offsets scan + aux loss ----------------
__global__ void scan_kernel(float* __restrict__ out, int out_size) {
    if (threadIdx.x == 0 && blockIdx.x == 0) {
        int o = 0;
        for (int e = 0; e < NE; e++) {
            g_off[e] = o;
            g_cur[e] = o;
            o += (g_cnt[e] + 127) & ~127;
        }
        g_off[NE] = o;
        float s = 0.0f;
        for (int e = 0; e < NE; e++) s += (float)g_cnt[e] * g_psum[e];
        float aux = 0.01f * (float)NE * s / ((float)T_TOK * (float)T_TOK);
        if (out_size > T_TOK * D_DIM) out[out_size - 1] = aux;
    }
}

// ---------------- token -> slot fill ----------------
__global__ void fill_kernel() {
    int t = blockIdx.x * blockDim.x + threadIdx.x;
    if (t >= T_TOK) return;
#pragma unroll
    for (int k = 0; k < 2; k++) {
        int e = g_topi[2 * t + k];
        int pos = atomicAdd(&g_cur[e], 1);
        g_rowlist[pos] = t;
        g_slot[2 * t + k] = pos;
    }
}

// ---------------- gather padded A (fp16) ----------------
__global__ void gather_kernel() {
    int slot = blockIdx.x;
    if (slot >= g_off[NE]) return;
    int e = 0;
    while (g_off[e + 1] <= slot) e++;
    int local = slot - g_off[e];
    int tid = threadIdx.x;
    uint4* dst = (uint4*)(g_Xg + (size_t)slot * D_DIM);
    if (local < g_cnt[e]) {
        int tok = g_rowlist[slot];
        const uint4* src = (const uint4*)(g_Xh + (size_t)tok * D_DIM);
        dst[tid] = src[tid];
    } else {
        dst[tid] = make_uint4(0, 0, 0, 0);
    }
}

// ---------------- GEMM1: H = silu(A@Wg^T)*(A@Wu^T), 4-stage pipeline ----------------
// CTA: 128 tokens x 64 I-cols (both matrices). blockIdx.x = tile (fast), .y = colblock.
__global__ void __launch_bounds__(256) gemm1_kernel() {
    const int t = blockIdx.x;
    const __half *Abase, *Bg, *Bu;
    if (t < EXP_TILES) {
        if (t * 128 >= g_off[NE]) return;
        int e = 0;
        while (g_off[e + 1] <= t * 128) e++;
        Abase = g_Xg + (size_t)t * 128 * D_DIM;
        size_t wo = (size_t)e * I_DIM * D_DIM;
        Bg = g_Wg + wo; Bu = g_Wu + wo;
    } else {
        Abase = g_Xh + (size_t)(t - EXP_TILES) * 128 * D_DIM;
        Bg = g_Sg; Bu = g_Su;
    }
    const int col0 = blockIdx.y * 64;

    extern __shared__ __align__(16) __half smem[];
    const int tid = threadIdx.x;
    const uint32_t smem_b = (uint32_t)__cvta_generic_to_shared(smem);

    // per-thread 4 transfers/stage: i in [0,1024)
    const __half* srcp[4];
    uint32_t dsto[4];
#pragma unroll
    for (int j = 0; j < 4; j++) {
        int i = tid + 256 * j;
        int r = i >> 2, seg = i & 3;
        const __half* bp;
        uint32_t off;
        if (r < 128)      { bp = Abase + (size_t)r * D_DIM;              off = (uint32_t)r * 80u; }
        else if (r < 192) { bp = Bg + (size_t)(col0 + r - 128) * D_DIM;  off = 10240u + (uint32_t)(r - 128) * 80u; }
        else              { bp = Bu + (size_t)(col0 + r - 192) * D_DIM;  off = 15360u + (uint32_t)(r - 192) * 80u; }
        srcp[j] = bp + seg * 8;
        dsto[j] = off + (uint32_t)seg * 16u;
    }

    const int wid = tid >> 5, lane = tid & 31;
    const int wm = wid >> 1, wn = wid & 1;

    wmma::fragment<wmma::accumulator, 16, 16, 16, float> accG[2][2], accU[2][2];
#pragma unroll
    for (int i = 0; i < 2; i++)
#pragma unroll
        for (int j = 0; j < 2; j++) {
            wmma::fill_fragment(accG[i][j], 0.0f);
            wmma::fill_fragment(accU[i][j], 0.0f);
        }

    // prologue: chunks 0..ST-2
#pragma unroll
    for (int pre = 0; pre < ST - 1; pre++) {
        uint32_t sb = smem_b + pre * (STAGE_HALFS * 2);
#pragma unroll
        for (int j = 0; j < 4; j++) cpa16(sb + dsto[j], srcp[j] + pre * 32);
        cp_commit();
    }

    const int nK = D_DIM / 32;   // 64
    for (int kt = 0; kt < nK; kt++) {
        cp_wait<ST - 2>();
        __syncthreads();
        int lc = kt + ST - 1;
        if (lc < nK) {
            uint32_t sb = smem_b + (lc & (ST - 1)) * (STAGE_HALFS * 2);
#pragma unroll
            for (int j = 0; j < 4; j++) cpa16(sb + dsto[j], srcp[j] + lc * 32);
        }
        cp_commit();

        const __half* A  = smem + (kt & (ST - 1)) * STAGE_HALFS;
        const __half* BG = A + 5120;
        const __half* BU = A + 7680;
#pragma unroll
        for (int kk = 0; kk < 32; kk += 16) {
            wmma::fragment<wmma::matrix_a, 16, 16, 16, __half, wmma::row_major> af[2];
            wmma::fragment<wmma::matrix_b, 16, 16, 16, __half, wmma::col_major> bgf[2], buf_[2];
            wmma::load_matrix_sync(af[0], A + (wm * 32 + 0) * 40 + kk, 40);
            wmma::load_matrix_sync(af[1], A + (wm * 32 + 16) * 40 + kk, 40);
            wmma::load_matrix_sync(bgf[0], BG + (wn * 32 + 0) * 40 + kk, 40);
            wmma::load_matrix_sync(bgf[1], BG + (wn * 32 + 16) * 40 + kk, 40);
            wmma::load_matrix_sync(buf_[0], BU + (wn * 32 + 0) * 40 + kk, 40);
            wmma::load_matrix_sync(buf_[1], BU + (wn * 32 + 16) * 40 + kk, 40);
#pragma unroll
            for (int i = 0; i < 2; i++)
#pragma unroll
                for (int j = 0; j < 2; j++) {
                    wmma::mma_sync(accG[i][j], af[i], bgf[j], accG[i][j]);
                    wmma::mma_sync(accU[i][j], af[i], buf_[j], accU[i][j]);
                }
        }
    }
    __syncthreads();   // before scratch reuse

    // epilogue: h = silu(g) * u -> fp16
    float* scr = reinterpret_cast<float*>(smem) + wid * (32 * 36);
    wmma::fragment<wmma::accumulator, 16, 16, 16, float> hf;
#pragma unroll
    for (int i = 0; i < 2; i++)
#pragma unroll
        for (int j = 0; j < 2; j++) {
#pragma unroll
            for (int e = 0; e < hf.num_elements; e++) {
                float g = accG[i][j].x[e];
                float u = accU[i][j].x[e];
                hf.x[e] = (g / (1.0f + __expf(-g))) * u;
            }
            wmma::store_matrix_sync(scr + (i * 16) * 36 + j * 16, hf, 36, wmma::mem_row_major);
        }
    __syncwarp();

    size_t hrow = (size_t)t * 128 + wm * 32 + lane;
    const float* srow = scr + lane * 36;
    __half2 hh[16];
#pragma unroll
    for (int c = 0; c < 16; c++) hh[c] = __floats2half2_rn(srow[2 * c], srow[2 * c + 1]);
    uint4* dst = (uint4*)(g_H + hrow * I_DIM + col0 + wn * 32);
    const uint4* s4 = (const uint4*)hh;
    dst[0] = s4[0]; dst[1] = s4[1]; dst[2] = s4[2]; dst[3] = s4[3];
}

// ---------------- GEMM2: Y = H @ Wd^T, 4-stage pipeline ----------------
// CTA: 128 rows x 128 D-cols. blockIdx.x = tile (fast), .y = colblock.
__global__ void __launch_bounds__(256) gemm2_kernel() {
    const int t = blockIdx.x;
    if (t < EXP_TILES && t * 128 >= g_off[NE]) return;
    const __half* Bd;
    if (t < EXP_TILES) {
        int e = 0;
        while (g_off[e + 1] <= t * 128) e++;
        Bd = g_Wd + (size_t)e * D_DIM * I_DIM;
    } else {
        Bd = g_Sd;
    }
    const __half* Abase = g_H + (size_t)t * 128 * I_DIM;
    const int col0 = blockIdx.y * 128;

    extern __shared__ __align__(16) __half smem[];
    const int tid = threadIdx.x;
    const uint32_t smem_b = (uint32_t)__cvta_generic_to_shared(smem);

    const __half* srcp[4];
    uint32_t dsto[4];
#pragma unroll
    for (int j = 0; j < 4; j++) {
        int i = tid + 256 * j;
        int r = i >> 2, seg = i & 3;
        const __half* bp;
        uint32_t off;
        if (r < 128) { bp = Abase + (size_t)r * I_DIM;            off = (uint32_t)r * 80u; }
        else         { bp = Bd + (size_t)(col0 + r - 128) * I_DIM; off = 10240u + (uint32_t)(r - 128) * 80u; }
        srcp[j] = bp + seg * 8;
        dsto[j] = off + (uint32_t)seg * 16u;
    }

    const int wid = tid >> 5;
    const int wm = wid >> 1, wn = wid & 1;

    wmma::fragment<wmma::accumulator, 16, 16, 16, float> acc[2][4];
#pragma unroll
    for (int i = 0; i < 2; i++)
#pragma unroll
        for (int j = 0; j < 4; j++) wmma::fill_fragment(acc[i][j], 0.0f);

#pragma unroll
    for (int pre = 0; pre < ST - 1; pre++) {
        uint32_t sb = smem_b + pre * (STAGE_HALFS * 2);
#pragma unroll
        for (int j = 0; j < 4; j++) cpa16(sb + dsto[j], srcp[j] + pre * 32);
        cp_commit();
    }

    const int nK = I_DIM / 32;   // 176
    for (int kt = 0; kt < nK; kt++) {
        cp_wait<ST - 2>();
        __syncthreads();
        int lc = kt + ST - 1;
        if (lc < nK) {
            uint32_t sb = smem_b + (lc & (ST - 1)) * (STAGE_HALFS * 2);
#pragma unroll
            for (int j = 0; j < 4; j++) cpa16(sb + dsto[j], srcp[j] + lc * 32);
        }
        cp_commit();

        const __half* A = smem + (kt & (ST - 1)) * STAGE_HALFS;
        const __half* B = A + 5120;
#pragma unroll
        for (int kk = 0; kk < 32; kk += 16) {
            wmma::fragment<wmma::matrix_a, 16, 16, 16, __half, wmma::row_major> af[2];
            wmma::fragment<wmma::matrix_b, 16, 16, 16, __half, wmma::col_major> bf[4];
            wmma::load_matrix_sync(af[0], A + (wm * 32 + 0) * 40 + kk, 40);
            wmma::load_matrix_sync(af[1], A + (wm * 32 + 16) * 40 + kk, 40);
#pragma unroll
            for (int j = 0; j < 4; j++)
                wmma::load_matrix_sync(bf[j], B + (wn * 64 + j * 16) * 40 + kk, 40);
#pragma unroll
            for (int i = 0; i < 2; i++)
#pragma unroll
                for (int j = 0; j < 4; j++)
                    wmma::mma_sync(acc[i][j], af[i], bf[j], acc[i][j]);
        }
    }

    const int rowb = t * 128 + wm * 32;
    const int colb = col0 + wn * 64;
#pragma unroll
    for (int i = 0; i < 2; i++)
#pragma unroll
        for (int j = 0; j < 4; j++)
            wmma::store_matrix_sync(&g_Y[(size_t)(rowb + i * 16) * D_DIM + colb + j * 16],
                                    acc[i][j], D_DIM, wmma::mem_row_major);
}

// ---------------- combine ----------------
__global__ void combine_kernel(float* __restrict__ out) {
    const float4* Y4 = (const float4*)g_Y;
    float4* o4 = (float4*)out;
    int stride = gridDim.x * blockDim.x;
    const int total = T_TOK * (D_DIM / 4);
    for (int i = blockIdx.x * blockDim.x + threadIdx.x; i < total; i += stride) {
        int t = i >> 9;
        int d = i & 511;
        int s0 = g_slot[2 * t], s1 = g_slot[2 * t + 1];
        float w0 = g_topw[2 * t], w1 = g_topw[2 * t + 1];
        float4 ys = Y4[(size_t)(SHARED_BASE + t) * 512 + d];
        float4 y0 = Y4[(size_t)s0 * 512 + d];
        float4 y1 = Y4[(size_t)s1 * 512 + d];
        float4 r;
        r.x = ys.x + w0 * y0.x + w1 * y1.x;
        r.y = ys.y + w0 * y0.y + w1 * y1.y;
        r.z = ys.z + w0 * y0.z + w1 * y1.z;
        r.w = ys.w + w0 * y0.w + w1 * y1.w;
        o4[i] = r;
    }
}

// ---------------- launch ----------------
extern "C" void kernel_launch(void* const* d_in, const int* in_sizes, int n_in,
                              void* d_out, int out_size) {
    const float* x  = (const float*)d_in[0];
    const float* gw = (const float*)d_in[1];
    const float* eg = (const float*)d_in[2];
    const float* eu = (const float*)d_in[3];
    const float* ed = (const float*)d_in[4];
    const float* sg = (const float*)d_in[5];
    const float* su = (const float*)d_in[6];
    const float* sd = (const float*)d_in[7];
    float* out = (float*)d_out;

    cudaFuncSetAttribute(gemm1_kernel, cudaFuncAttributeMaxDynamicSharedMemorySize, SMEM_DYN);
    cudaFuncSetAttribute(gemm2_kernel, cudaFuncAttributeMaxDynamicSharedMemorySize, SMEM_DYN);

    init_kernel<<<1, 32>>>();

    cvt_kernel<<<4096, 256>>>(x, 0, T_TOK * D_DIM);
    router_kernel<<<1024, 256>>>(x, gw);
    scan_kernel<<<1, 32>>>(out, out_size);
    fill_kernel<<<32, 256>>>();

    cvt_kernel<<<8192, 256>>>(eg, 1, NE * I_DIM * D_DIM);
    cvt_kernel<<<8192, 256>>>(eu, 2, NE * I_DIM * D_DIM);
    cvt_kernel<<<8192, 256>>>(ed, 3, NE * D_DIM * I_DIM);
    cvt_kernel<<<2048, 256>>>(sg, 4, I_DIM * D_DIM);
    cvt_kernel<<<2048, 256>>>(su, 5, I_DIM * D_DIM);
    cvt_kernel<<<2048, 256>>>(sd, 6, D_DIM * I_DIM);

    gather_kernel<<<SHARED_BASE, 256>>>();

    gemm1_kernel<<<dim3(TILES_TOTAL, I_DIM / 64), 256, SMEM_DYN>>>();
    gemm2_kernel<<<dim3(TILES_TOTAL, D_DIM / 128), 256, SMEM_DYN>>>();

    combine_kernel<<<8192, 256>>>(out);
}

// round 5
// speedup vs baseline: 1.2777x; 1.0180x over previous
#include <cuda_runtime.h>
#include <cuda_fp16.h>
#include <mma.h>
#include <math.h>
#include <stdint.h>

using namespace nvcuda;

// ---------------- problem constants ----------------
#define D_DIM   2048
#define I_DIM   5632
#define NE      8
#define T_TOK   8192
#define EXP_TILES  136
#define SHARED_BASE (EXP_TILES * 128)          // 17408
#define TILES_TOTAL (EXP_TILES + T_TOK / 128)  // 200
#define TOT_ROWS   (SHARED_BASE + T_TOK)       // 25600

#define ST 4                     // pipeline stages
#define STAGE_HALFS 10240        // per-stage smem halfs (20 KB)
#define SMEM_DYN    (ST * STAGE_HALFS * 2)     // 81920 B

// ---------------- static device scratch ----------------
__device__ __half g_Xh[(size_t)T_TOK * D_DIM];
__device__ __half g_Xg[(size_t)SHARED_BASE * D_DIM];   // gathered + zero-padded expert A
__device__ __half g_Wg[(size_t)NE * I_DIM * D_DIM];
__device__ __half g_Wu[(size_t)NE * I_DIM * D_DIM];
__device__ __half g_Wd[(size_t)NE * D_DIM * I_DIM];
__device__ __half g_Sg[(size_t)I_DIM * D_DIM];
__device__ __half g_Su[(size_t)I_DIM * D_DIM];
__device__ __half g_Sd[(size_t)D_DIM * I_DIM];
__device__ __half g_H [(size_t)TOT_ROWS * I_DIM];
__device__ float  g_Y [(size_t)TOT_ROWS * D_DIM];

__device__ int    g_cnt[NE];
__device__ int    g_off[NE + 1];
__device__ int    g_cur[NE];
__device__ float  g_psum[NE];
__device__ int    g_topi[T_TOK * 2];
__device__ float  g_topw[T_TOK * 2];
__device__ int    g_slot[T_TOK * 2];
__device__ int    g_rowlist[SHARED_BASE];

// ---------------- helpers ----------------
__device__ __forceinline__ void cpa16(uint32_t dst, const __half* src) {
    asm volatile("cp.async.cg.shared.global [%0], [%1], 16;\n" :: "r"(dst), "l"(src));
}
template <int N>
__device__ __forceinline__ void cp_wait() {
    asm volatile("cp.async.wait_group %0;\n" :: "n"(N));
}
__device__ __forceinline__ void cp_commit() {
    asm volatile("cp.async.commit_group;\n");
}

// ---------------- init ----------------
__global__ void init_kernel() {
    int i = threadIdx.x;
    if (i < NE) { g_cnt[i] = 0; g_psum[i] = 0.0f; }
}

// ---------------- f32 -> fp16 conversion ----------------
__device__ __forceinline__ __half* cvt_dst(int w) {
    switch (w) {
        case 0: return g_Xh;
        case 1: return g_Wg;
        case 2: return g_Wu;
        case 3: return g_Wd;
        case 4: return g_Sg;
        case 5: return g_Su;
        default: return g_Sd;
    }
}
__global__ void cvt_kernel(const float* __restrict__ src, int which, int n) {
    __half* dst = cvt_dst(which);
    int stride = gridDim.x * blockDim.x;
    for (int i = blockIdx.x * blockDim.x + threadIdx.x; i * 4 < n; i += stride) {
        int j = i * 4;
        float4 v = *(const float4*)(src + j);
        __half2* d2 = (__half2*)(dst + j);
        d2[0] = __floats2half2_rn(v.x, v.y);
        d2[1] = __floats2half2_rn(v.z, v.w);
    }
}

// ---------------- router ----------------
__global__ void router_kernel(const float* __restrict__ x, const float* __restrict__ gw) {
    __shared__ int   scnt[NE];
    __shared__ float sps[NE];
    int tid = threadIdx.x;
    if (tid < NE) { scnt[tid] = 0; sps[tid] = 0.0f; }
    __syncthreads();

    int warp = tid >> 5, lane = tid & 31;
    int t = blockIdx.x * 8 + warp;

    float acc[NE];
#pragma unroll
    for (int e = 0; e < NE; e++) acc[e] = 0.0f;

    const float* xp = x + (size_t)t * D_DIM;
    for (int k = lane; k < D_DIM; k += 32) {
        float xv = xp[k];
#pragma unroll
        for (int e = 0; e < NE; e++) acc[e] += xv * __ldg(&gw[e * D_DIM + k]);
    }
#pragma unroll
    for (int e = 0; e < NE; e++) {
#pragma unroll
        for (int o = 16; o; o >>= 1) acc[e] += __shfl_down_sync(0xffffffffu, acc[e], o);
    }

    if (lane == 0) {
        int i0 = 0; float v0 = acc[0];
#pragma unroll
        for (int e = 1; e < NE; e++) if (acc[e] > v0) { v0 = acc[e]; i0 = e; }
        int i1 = -1; float v1 = -1e30f;
#pragma unroll
        for (int e = 0; e < NE; e++) if (e != i0 && acc[e] > v1) { v1 = acc[e]; i1 = e; }

        float e1 = expf(v1 - v0);
        float w0 = 1.0f / (1.0f + e1);
        float w1 = e1 * w0;
        g_topi[2 * t]     = i0;  g_topi[2 * t + 1] = i1;
        g_topw[2 * t]     = w0;  g_topw[2 * t + 1] = w1;
        atomicAdd(&scnt[i0], 1);
        atomicAdd(&scnt[i1], 1);

        float m = acc[0];
#pragma unroll
        for (int e = 1; e < NE; e++) m = fmaxf(m, acc[e]);
        float s = 0.0f;
        float pe[NE];
#pragma unroll
        for (int e = 0; e < NE; e++) { pe[e] = expf(acc[e] - m); s += pe[e]; }
        float inv = 1.0f / s;
#pragma unroll
        for (int e = 0; e < NE; e++) atomicAdd(&sps[e], pe[e] * inv);
    }
    __syncthreads();
    if (tid < NE) {
        atomicAdd(&g_cnt[tid], scnt[tid]);
        atomicAdd(&g_psum[tid], sps[tid]);
    }
}

// ---------------- offsets scan + aux loss ----------------
__global__ void scan_kernel(float* __restrict__ out, int out_size) {
    if (threadIdx.x == 0 && blockIdx.x == 0) {
        int o = 0;
        for (int e = 0; e < NE; e++) {
            g_off[e] = o;
            g_cur[e] = o;
            o += (g_cnt[e] + 127) & ~127;
        }
        g_off[NE] = o;
        float s = 0.0f;
        for (int e = 0; e < NE; e++) s += (float)g_cnt[e] * g_psum[e];
        float aux = 0.01f * (float)NE * s / ((float)T_TOK * (float)T_TOK);
        if (out_size > T_TOK * D_DIM) out[out_size - 1] = aux;
    }
}

// ---------------- token -> slot fill ----------------
__global__ void fill_kernel() {
    int t = blockIdx.x * blockDim.x + threadIdx.x;
    if (t >= T_TOK) return;
#pragma unroll
    for (int k = 0; k < 2; k++) {
        int e = g_topi[2 * t + k];
        int pos = atomicAdd(&g_cur[e], 1);
        g_rowlist[pos] = t;
        g_slot[2 * t + k] = pos;
    }
}

// ---------------- gather padded A (fp16) ----------------
__global__ void gather_kernel() {
    int slot = blockIdx.x;
    if (slot >= g_off[NE]) return;
    int e = 0;
    while (g_off[e + 1] <= slot) e++;
    int local = slot - g_off[e];
    int tid = threadIdx.x;
    uint4* dst = (uint4*)(g_Xg + (size_t)slot * D_DIM);
    if (local < g_cnt[e]) {
        int tok = g_rowlist[slot];
        const uint4* src = (const uint4*)(g_Xh + (size_t)tok * D_DIM);
        dst[tid] = src[tid];
    } else {
        dst[tid] = make_uint4(0, 0, 0, 0);
    }
}

// ---------------- GEMM1: H = silu(A@Wg^T)*(A@Wu^T) ----------------
// 128 threads, 2x2 warp grid, warp tile 64 rows x (32 gate + 32 up) cols.
// CTA output: 128 tokens x 64 I-cols. 4-stage cp.async pipeline.
__global__ void __launch_bounds__(128) gemm1_kernel() {
    const int t = blockIdx.x;
    const __half *Abase, *Bg, *Bu;
    if (t < EXP_TILES) {
        if (t * 128 >= g_off[NE]) return;
        int e = 0;
        while (g_off[e + 1] <= t * 128) e++;
        Abase = g_Xg + (size_t)t * 128 * D_DIM;
        size_t wo = (size_t)e * I_DIM * D_DIM;
        Bg = g_Wg + wo; Bu = g_Wu + wo;
    } else {
        Abase = g_Xh + (size_t)(t - EXP_TILES) * 128 * D_DIM;
        Bg = g_Sg; Bu = g_Su;
    }
    const int col0 = blockIdx.y * 64;

    extern __shared__ __align__(16) __half smem[];
    const int tid = threadIdx.x;
    const uint32_t smem_b = (uint32_t)__cvta_generic_to_shared(smem);

    // per-thread 8 transfers/stage: 1024 = 256 rows x 4 segs of 16B
    const __half* srcp[8];
    uint32_t dsto[8];
#pragma unroll
    for (int j = 0; j < 8; j++) {
        int i = tid + 128 * j;
        int r = i >> 2, seg = i & 3;
        const __half* bp;
        uint32_t off;
        if (r < 128)      { bp = Abase + (size_t)r * D_DIM;              off = (uint32_t)r * 80u; }
        else if (r < 192) { bp = Bg + (size_t)(col0 + r - 128) * D_DIM;  off = 10240u + (uint32_t)(r - 128) * 80u; }
        else              { bp = Bu + (size_t)(col0 + r - 192) * D_DIM;  off = 15360u + (uint32_t)(r - 192) * 80u; }
        srcp[j] = bp + seg * 8;
        dsto[j] = off + (uint32_t)seg * 16u;
    }

    const int wid = tid >> 5, lane = tid & 31;
    const int wm = wid >> 1, wn = wid & 1;

    wmma::fragment<wmma::accumulator, 16, 16, 16, float> accG[4][2], accU[4][2];
#pragma unroll
    for (int i = 0; i < 4; i++)
#pragma unroll
        for (int j = 0; j < 2; j++) {
            wmma::fill_fragment(accG[i][j], 0.0f);
            wmma::fill_fragment(accU[i][j], 0.0f);
        }

#pragma unroll
    for (int pre = 0; pre < ST - 1; pre++) {
        uint32_t sb = smem_b + pre * (STAGE_HALFS * 2);
#pragma unroll
        for (int j = 0; j < 8; j++) cpa16(sb + dsto[j], srcp[j] + pre * 32);
        cp_commit();
    }

    const int nK = D_DIM / 32;   // 64
    for (int kt = 0; kt < nK; kt++) {
        cp_wait<ST - 2>();
        __syncthreads();
        int lc = kt + ST - 1;
        if (lc < nK) {
            uint32_t sb = smem_b + (lc & (ST - 1)) * (STAGE_HALFS * 2);
#pragma unroll
            for (int j = 0; j < 8; j++) cpa16(sb + dsto[j], srcp[j] + lc * 32);
        }
        cp_commit();

        const __half* A  = smem + (kt & (ST - 1)) * STAGE_HALFS;
        const __half* BG = A + 5120;
        const __half* BU = A + 7680;
#pragma unroll
        for (int kk = 0; kk < 32; kk += 16) {
            wmma::fragment<wmma::matrix_a, 16, 16, 16, __half, wmma::row_major> af[4];
            wmma::fragment<wmma::matrix_b, 16, 16, 16, __half, wmma::col_major> bgf[2], buf_[2];
#pragma unroll
            for (int i = 0; i < 4; i++)
                wmma::load_matrix_sync(af[i], A + (wm * 64 + i * 16) * 40 + kk, 40);
#pragma unroll
            for (int j = 0; j < 2; j++) {
                wmma::load_matrix_sync(bgf[j], BG + (wn * 32 + j * 16) * 40 + kk, 40);
                wmma::load_matrix_sync(buf_[j], BU + (wn * 32 + j * 16) * 40 + kk, 40);
            }
#pragma unroll
            for (int i = 0; i < 4; i++)
#pragma unroll
                for (int j = 0; j < 2; j++) {
                    wmma::mma_sync(accG[i][j], af[i], bgf[j], accG[i][j]);
                    wmma::mma_sync(accU[i][j], af[i], buf_[j], accU[i][j]);
                }
        }
    }
    __syncthreads();   // before scratch reuse

    // epilogue: h = silu(g) * u -> fp16. Per-warp scratch 64 rows x 36 f32.
    float* scr = reinterpret_cast<float*>(smem) + wid * 2304;
    wmma::fragment<wmma::accumulator, 16, 16, 16, float> hf;
#pragma unroll
    for (int i = 0; i < 4; i++)
#pragma unroll
        for (int j = 0; j < 2; j++) {
#pragma unroll
            for (int e = 0; e < hf.num_elements; e++) {
                float g = accG[i][j].x[e];
                float u = accU[i][j].x[e];
                hf.x[e] = (g / (1.0f + __expf(-g))) * u;
            }
            wmma::store_matrix_sync(scr + (i * 16) * 36 + j * 16, hf, 36, wmma::mem_row_major);
        }
    __syncwarp();

#pragma unroll
    for (int h = 0; h < 2; h++) {
        int r = lane + h * 32;                       // warp-local row 0..63
        size_t hrow = (size_t)t * 128 + wm * 64 + r;
        const float* srow = scr + r * 36;
        __half2 hh[16];
#pragma unroll
        for (int c = 0; c < 16; c++) hh[c] = __floats2half2_rn(srow[2 * c], srow[2 * c + 1]);
        uint4* dst = (uint4*)(g_H + hrow * I_DIM + col0 + wn * 32);
        const uint4* s4 = (const uint4*)hh;
        dst[0] = s4[0]; dst[1] = s4[1]; dst[2] = s4[2]; dst[3] = s4[3];
    }
}

// ---------------- GEMM2: Y = H @ Wd^T ----------------
// 128 threads, 2x2 warp grid, warp tile 64x64. CTA: 128 rows x 128 D-cols.
__global__ void __launch_bounds__(128) gemm2_kernel() {
    const int t = blockIdx.x;
    if (t < EXP_TILES && t * 128 >= g_off[NE]) return;
    const __half* Bd;
    if (t < EXP_TILES) {
        int e = 0;
        while (g_off[e + 1] <= t * 128) e++;
        Bd = g_Wd + (size_t)e * D_DIM * I_DIM;
    } else {
        Bd = g_Sd;
    }
    const __half* Abase = g_H + (size_t)t * 128 * I_DIM;
    const int col0 = blockIdx.y * 128;

    extern __shared__ __align__(16) __half smem[];
    const int tid = threadIdx.x;
    const uint32_t smem_b = (uint32_t)__cvta_generic_to_shared(smem);

    const __half* srcp[8];
    uint32_t dsto[8];
#pragma unroll
    for (int j = 0; j < 8; j++) {
        int i = tid + 128 * j;
        int r = i >> 2, seg = i & 3;
        const __half* bp;
        uint32_t off;
        if (r < 128) { bp = Abase + (size_t)r * I_DIM;             off = (uint32_t)r * 80u; }
        else         { bp = Bd + (size_t)(col0 + r - 128) * I_DIM; off = 10240u + (uint32_t)(r - 128) * 80u; }
        srcp[j] = bp + seg * 8;
        dsto[j] = off + (uint32_t)seg * 16u;
    }

    const int wid = tid >> 5;
    const int wm = wid >> 1, wn = wid & 1;

    wmma::fragment<wmma::accumulator, 16, 16, 16, float> acc[4][4];
#pragma unroll
    for (int i = 0; i < 4; i++)
#pragma unroll
        for (int j = 0; j < 4; j++) wmma::fill_fragment(acc[i][j], 0.0f);

#pragma unroll
    for (int pre = 0; pre < ST - 1; pre++) {
        uint32_t sb = smem_b + pre * (STAGE_HALFS * 2);
#pragma unroll
        for (int j = 0; j < 8; j++) cpa16(sb + dsto[j], srcp[j] + pre * 32);
        cp_commit();
    }

    const int nK = I_DIM / 32;   // 176
    for (int kt = 0; kt < nK; kt++) {
        cp_wait<ST - 2>();
        __syncthreads();
        int lc = kt + ST - 1;
        if (lc < nK) {
            uint32_t sb = smem_b + (lc & (ST - 1)) * (STAGE_HALFS * 2);
#pragma unroll
            for (int j = 0; j < 8; j++) cpa16(sb + dsto[j], srcp[j] + lc * 32);
        }
        cp_commit();

        const __half* A = smem + (kt & (ST - 1)) * STAGE_HALFS;
        const __half* B = A + 5120;
#pragma unroll
        for (int kk = 0; kk < 32; kk += 16) {
            wmma::fragment<wmma::matrix_a, 16, 16, 16, __half, wmma::row_major> af[4];
            wmma::fragment<wmma::matrix_b, 16, 16, 16, __half, wmma::col_major> bf[4];
#pragma unroll
            for (int i = 0; i < 4; i++)
                wmma::load_matrix_sync(af[i], A + (wm * 64 + i * 16) * 40 + kk, 40);
#pragma unroll
            for (int j = 0; j < 4; j++)
                wmma::load_matrix_sync(bf[j], B + (wn * 64 + j * 16) * 40 + kk, 40);
#pragma unroll
            for (int i = 0; i < 4; i++)
#pragma unroll
                for (int j = 0; j < 4; j++)
                    wmma::mma_sync(acc[i][j], af[i], bf[j], acc[i][j]);
        }
    }

    const int rowb = t * 128 + wm * 64;
    const int colb = col0 + wn * 64;
#pragma unroll
    for (int i = 0; i < 4; i++)
#pragma unroll
        for (int j = 0; j < 4; j++)
            wmma::store_matrix_sync(&g_Y[(size_t)(rowb + i * 16) * D_DIM + colb + j * 16],
                                    acc[i][j], D_DIM, wmma::mem_row_major);
}

// ---------------- combine ----------------
__global__ void combine_kernel(float* __restrict__ out) {
    const float4* Y4 = (const float4*)g_Y;
    float4* o4 = (float4*)out;
    int stride = gridDim.x * blockDim.x;
    const int total = T_TOK * (D_DIM / 4);
    for (int i = blockIdx.x * blockDim.x + threadIdx.x; i < total; i += stride) {
        int t = i >> 9;
        int d = i & 511;
        int s0 = g_slot[2 * t], s1 = g_slot[2 * t + 1];
        float w0 = g_topw[2 * t], w1 = g_topw[2 * t + 1];
        float4 ys = Y4[(size_t)(SHARED_BASE + t) * 512 + d];
        float4 y0 = Y4[(size_t)s0 * 512 + d];
        float4 y1 = Y4[(size_t)s1 * 512 + d];
        float4 r;
        r.x = ys.x + w0 * y0.x + w1 * y1.x;
        r.y = ys.y + w0 * y0.y + w1 * y1.y;
        r.z = ys.z + w0 * y0.z + w1 * y1.z;
        r.w = ys.w + w0 * y0.w + w1 * y1.w;
        o4[i] = r;
    }
}

// ---------------- launch ----------------
extern "C" void kernel_launch(void* const* d_in, const int* in_sizes, int n_in,
                              void* d_out, int out_size) {
    const float* x  = (const float*)d_in[0];
    const float* gw = (const float*)d_in[1];
    const float* eg = (const float*)d_in[2];
    const float* eu = (const float*)d_in[3];
    const float* ed = (const float*)d_in[4];
    const float* sg = (const float*)d_in[5];
    const float* su = (const float*)d_in[6];
    const float* sd = (const float*)d_in[7];
    float* out = (float*)d_out;

    cudaFuncSetAttribute(gemm1_kernel, cudaFuncAttributeMaxDynamicSharedMemorySize, SMEM_DYN);
    cudaFuncSetAttribute(gemm2_kernel, cudaFuncAttributeMaxDynamicSharedMemorySize, SMEM_DYN);

    init_kernel<<<1, 32>>>();

    cvt_kernel<<<4096, 256>>>(x, 0, T_TOK * D_DIM);
    router_kernel<<<1024, 256>>>(x, gw);
    scan_kernel<<<1, 32>>>(out, out_size);
    fill_kernel<<<32, 256>>>();

    cvt_kernel<<<8192, 256>>>(eg, 1, NE * I_DIM * D_DIM);
    cvt_kernel<<<8192, 256>>>(eu, 2, NE * I_DIM * D_DIM);
    cvt_kernel<<<8192, 256>>>(ed, 3, NE * D_DIM * I_DIM);
    cvt_kernel<<<2048, 256>>>(sg, 4, I_DIM * D_DIM);
    cvt_kernel<<<2048, 256>>>(su, 5, I_DIM * D_DIM);
    cvt_kernel<<<2048, 256>>>(sd, 6, D_DIM * I_DIM);

    gather_kernel<<<SHARED_BASE, 256>>>();

    gemm1_kernel<<<dim3(TILES_TOTAL, I_DIM / 64), 128, SMEM_DYN>>>();
    gemm2_kernel<<<dim3(TILES_TOTAL, D_DIM / 128), 128, SMEM_DYN>>>();

    combine_kernel<<<8192, 256>>>(out);
}